// round 2
// baseline (speedup 1.0000x reference)
#include <cuda_runtime.h>
#include <cuda_bf16.h>
#include <math.h>

// ---------------------------------------------------------------------------
// ATT_HGCN: 2-layer attention GCN, fully fused pipeline.
//   N=100000 nodes, E=1600000 edges, D_IN=D_HID=128, D_OUT=64, ATT=64, G=64
// Output layout (float32, 400064 elems):
//   [0:64)                graph_embd (G,1)
//   [64 : 64+2N)          att1 (N,2) row-major
//   [64+2N : 64+4N)       att2 (N,2) row-major
// ---------------------------------------------------------------------------

static constexpr int NN = 100000;
static constexpr int EE = 1600000;
static constexpr int GG = 64;

// ---------------- scratch (static __device__ — no allocations) -------------
__device__ float g_self1[(size_t)NN * 128];
__device__ float g_rel1 [(size_t)NN * 128];
__device__ float g_h1   [(size_t)NN * 128];
__device__ float g_self2[(size_t)NN * 64];
__device__ float g_rel2 [(size_t)NN * 64];

__device__ int   g_deg[NN];
__device__ int   g_rowptr[NN + 1];
__device__ int   g_cursor[NN];
__device__ int   g_bsum[64];
__device__ int   g_csr_src[EE];
__device__ float g_csr_w[EE];

__device__ float g_vk1[128], g_vq1[128], g_vk2[64], g_vq2[64];
__device__ float g_gsum[GG * 64];
__device__ int   g_gcnt[GG];

__device__ __forceinline__ float eluf(float v) {
    return v > 0.f ? v : (__expf(v) - 1.f);
}

// ---------------- small setup kernels ---------------------------------------
__global__ void zero_k() {
    int i = blockIdx.x * blockDim.x + threadIdx.x;
    if (i < NN) g_deg[i] = 0;
    if (i < GG * 64) g_gsum[i] = 0.f;
    if (i < GG) g_gcnt[i] = 0;
}

// vk = w_k @ a[:ATT], vq = w_q @ a[ATT:]
__global__ void prep_k(const float* __restrict__ wq1, const float* __restrict__ wk1,
                       const float* __restrict__ watt1,
                       const float* __restrict__ wq2, const float* __restrict__ wk2,
                       const float* __restrict__ watt2) {
    int d = threadIdx.x;
    if (d < 128) {
        float sk = 0.f, sq = 0.f;
        for (int a = 0; a < 64; a++) {
            sk = fmaf(wk1[d * 64 + a], watt1[a], sk);
            sq = fmaf(wq1[d * 64 + a], watt1[64 + a], sq);
        }
        g_vk1[d] = sk; g_vq1[d] = sq;
    }
    if (d < 64) {
        float sk = 0.f, sq = 0.f;
        for (int a = 0; a < 64; a++) {
            sk = fmaf(wk2[d * 64 + a], watt2[a], sk);
            sq = fmaf(wq2[d * 64 + a], watt2[64 + a], sq);
        }
        g_vk2[d] = sk; g_vq2[d] = sq;
    }
}

__global__ void hist_k(const int* __restrict__ edst, const int* __restrict__ gid) {
    int i = blockIdx.x * blockDim.x + threadIdx.x;
    if (i < EE) atomicAdd(&g_deg[edst[i]], 1);
    if (i < NN) atomicAdd(&g_gcnt[gid[i]], 1);
}

// -------- exclusive scan of g_deg -> g_rowptr (3 phases, 2048 elems/block) ---
__global__ void scanA_k() {
    __shared__ int sh[256];
    int tid = threadIdx.x;
    int base = blockIdx.x * 2048 + tid * 8;
    int v[8]; int run = 0;
#pragma unroll
    for (int j = 0; j < 8; j++) {
        int idx = base + j;
        int d = (idx < NN) ? g_deg[idx] : 0;
        v[j] = run; run += d;
    }
    sh[tid] = run;
    __syncthreads();
    for (int off = 1; off < 256; off <<= 1) {
        int t = (tid >= off) ? sh[tid - off] : 0;
        __syncthreads();
        sh[tid] += t;
        __syncthreads();
    }
    int excl = sh[tid] - run;
#pragma unroll
    for (int j = 0; j < 8; j++) {
        int idx = base + j;
        if (idx < NN) g_rowptr[idx] = excl + v[j];
    }
    if (tid == 255) g_bsum[blockIdx.x] = sh[255];
}

__global__ void scanB_k(int nb) {
    if (threadIdx.x == 0 && blockIdx.x == 0) {
        int run = 0;
        for (int i = 0; i < nb; i++) { int t = g_bsum[i]; g_bsum[i] = run; run += t; }
    }
}

__global__ void scanC_k() {
    int i = blockIdx.x * blockDim.x + threadIdx.x;
    if (i < NN) {
        int r = g_rowptr[i] + g_bsum[i >> 11];
        g_rowptr[i] = r;
        g_cursor[i] = r;
    }
    if (i == 0) g_rowptr[NN] = EE;
}

__global__ void fill_k(const int* __restrict__ esrc, const int* __restrict__ edst,
                       const float* __restrict__ ew) {
    int e = blockIdx.x * blockDim.x + threadIdx.x;
    if (e >= EE) return;
    int d = edst[e];
    int pos = atomicAdd(&g_cursor[d], 1);
    g_csr_src[pos] = esrc[e];
    g_csr_w[pos]   = ew[e];
}

// ---------------- fused GEMM: C = X @ W, split across two halves ------------
// X: [NN][128]  (layer==0: harness x; layer==1: g_h1)
// Wa/Wb: [128][half] each.  Column tile picks Wa or Wb. 64x64 tile, 4x4/thread.
__global__ void __launch_bounds__(256, 4)
gemm_k(const float* __restrict__ Xext, int layer,
       const float* __restrict__ Wa, const float* __restrict__ Wb, int half) {
    const float* __restrict__ X = (layer == 0) ? Xext : g_h1;
    float* Ca = (layer == 0) ? g_self1 : g_self2;
    float* Cb = (layer == 0) ? g_rel1  : g_rel2;

    int colbase = blockIdx.y * 64;
    const float* __restrict__ W;
    float* C; int cb;
    if (colbase < half) { W = Wa; C = Ca; cb = colbase; }
    else                { W = Wb; C = Cb; cb = colbase - half; }

    __shared__ float xs[64][66];   // [m][k] padded: compute reads conflict-free
    __shared__ float ws[64][64];   // [k][n]

    int tid = threadIdx.x;
    int tx = tid & 15, ty = tid >> 4;
    int m0 = blockIdx.x * 64;
    int ty4 = ty * 4, tx4 = tx * 4;

    float acc[4][4] = {};

    for (int kc = 0; kc < 128; kc += 64) {
        // stage X tile (64 rows x 64 k-cols), coalesced gmem float4
#pragma unroll
        for (int li = tid; li < 1024; li += 256) {
            int r = li >> 4, c4 = (li & 15) << 2;
            int gm = m0 + r;
            float4 v = make_float4(0.f, 0.f, 0.f, 0.f);
            if (gm < NN) v = *(const float4*)(X + (size_t)gm * 128 + kc + c4);
            xs[r][c4] = v.x; xs[r][c4 + 1] = v.y; xs[r][c4 + 2] = v.z; xs[r][c4 + 3] = v.w;
        }
        // stage W tile (64 k-rows x 64 cols)
#pragma unroll
        for (int li = tid; li < 1024; li += 256) {
            int r = li >> 4, c4 = (li & 15) << 2;
            *(float4*)(&ws[r][c4]) = *(const float4*)(W + (size_t)(kc + r) * half + cb + c4);
        }
        __syncthreads();
#pragma unroll 16
        for (int k = 0; k < 64; k++) {
            float xf0 = xs[ty4 + 0][k];
            float xf1 = xs[ty4 + 1][k];
            float xf2 = xs[ty4 + 2][k];
            float xf3 = xs[ty4 + 3][k];
            float4 wv = *(const float4*)(&ws[k][tx4]);
            acc[0][0] = fmaf(xf0, wv.x, acc[0][0]); acc[0][1] = fmaf(xf0, wv.y, acc[0][1]);
            acc[0][2] = fmaf(xf0, wv.z, acc[0][2]); acc[0][3] = fmaf(xf0, wv.w, acc[0][3]);
            acc[1][0] = fmaf(xf1, wv.x, acc[1][0]); acc[1][1] = fmaf(xf1, wv.y, acc[1][1]);
            acc[1][2] = fmaf(xf1, wv.z, acc[1][2]); acc[1][3] = fmaf(xf1, wv.w, acc[1][3]);
            acc[2][0] = fmaf(xf2, wv.x, acc[2][0]); acc[2][1] = fmaf(xf2, wv.y, acc[2][1]);
            acc[2][2] = fmaf(xf2, wv.z, acc[2][2]); acc[2][3] = fmaf(xf2, wv.w, acc[2][3]);
            acc[3][0] = fmaf(xf3, wv.x, acc[3][0]); acc[3][1] = fmaf(xf3, wv.y, acc[3][1]);
            acc[3][2] = fmaf(xf3, wv.z, acc[3][2]); acc[3][3] = fmaf(xf3, wv.w, acc[3][3]);
        }
        __syncthreads();
    }
#pragma unroll
    for (int i = 0; i < 4; i++) {
        int gm = m0 + ty4 + i;
        if (gm < NN) {
            float4 v = make_float4(acc[i][0], acc[i][1], acc[i][2], acc[i][3]);
            *(float4*)(C + (size_t)gm * half + cb + tx4) = v;
        }
    }
}

// ------------- fused SpMM gather + attention + elu, layer 1 (D=128) ---------
// One warp per dst node; nb row lives in registers (4 floats/lane).
__global__ void spmm_att1_k(const float* __restrict__ bias, float* __restrict__ att_out) {
    int w = (blockIdx.x * blockDim.x + threadIdx.x) >> 5;
    int lane = threadIdx.x & 31;
    if (w >= NN) return;

    int beg = g_rowptr[w], end = g_rowptr[w + 1];
    float4 acc = make_float4(0.f, 0.f, 0.f, 0.f);
    const float* __restrict__ relbase = g_rel1 + lane * 4;

    for (int e0 = beg; e0 < end; e0 += 32) {
        int e = e0 + lane;
        int s = 0; float wt = 0.f;
        if (e < end) { s = g_csr_src[e]; wt = g_csr_w[e]; }
        int cnt = min(32, end - e0);
#pragma unroll 4
        for (int j = 0; j < cnt; j++) {
            int   ss = __shfl_sync(0xffffffffu, s,  j);
            float ww = __shfl_sync(0xffffffffu, wt, j);
            float4 r = *(const float4*)(relbase + (size_t)ss * 128);
            acc.x = fmaf(ww, r.x, acc.x);
            acc.y = fmaf(ww, r.y, acc.y);
            acc.z = fmaf(ww, r.z, acc.z);
            acc.w = fmaf(ww, r.w, acc.w);
        }
    }

    float4 sf = *(const float4*)(g_self1 + (size_t)w * 128 + lane * 4);
    float4 kv = *(const float4*)(g_vk1 + lane * 4);
    float4 qv = *(const float4*)(g_vq1 + lane * 4);

    float dsk = sf.x * kv.x + sf.y * kv.y + sf.z * kv.z + sf.w * kv.w;
    float dnk = acc.x * kv.x + acc.y * kv.y + acc.z * kv.z + acc.w * kv.w;
    float dsq = sf.x * qv.x + sf.y * qv.y + sf.z * qv.z + sf.w * qv.w;
#pragma unroll
    for (int off = 16; off; off >>= 1) {
        dsk += __shfl_xor_sync(0xffffffffu, dsk, off);
        dnk += __shfl_xor_sync(0xffffffffu, dnk, off);
        dsq += __shfl_xor_sync(0xffffffffu, dsq, off);
    }
    float es = eluf(dsk + dsq);
    float en = eluf(dnk + dsq);
    float m = fmaxf(es, en);
    float xe = __expf(es - m), ne = __expf(en - m);
    float inv = 1.f / (xe + ne);
    float a0 = xe * inv, a1 = ne * inv;

    float4 b = *(const float4*)(bias + lane * 4);
    float4 o;
    o.x = eluf(fmaf(a0, sf.x, fmaf(a1, acc.x, b.x)));
    o.y = eluf(fmaf(a0, sf.y, fmaf(a1, acc.y, b.y)));
    o.z = eluf(fmaf(a0, sf.z, fmaf(a1, acc.z, b.z)));
    o.w = eluf(fmaf(a0, sf.w, fmaf(a1, acc.w, b.w)));
    *(float4*)(g_h1 + (size_t)w * 128 + lane * 4) = o;

    if (lane == 0) { att_out[2 * w] = a0; att_out[2 * w + 1] = a1; }
}

// ------- fused SpMM + attention, layer 2 (D=64) + graph-sum pooling ---------
__global__ void spmm_att2_k(const float* __restrict__ bias, const int* __restrict__ gid,
                            float* __restrict__ att_out) {
    int w = (blockIdx.x * blockDim.x + threadIdx.x) >> 5;
    int lane = threadIdx.x & 31;
    if (w >= NN) return;

    int beg = g_rowptr[w], end = g_rowptr[w + 1];
    float2 acc = make_float2(0.f, 0.f);
    const float* __restrict__ relbase = g_rel2 + lane * 2;

    for (int e0 = beg; e0 < end; e0 += 32) {
        int e = e0 + lane;
        int s = 0; float wt = 0.f;
        if (e < end) { s = g_csr_src[e]; wt = g_csr_w[e]; }
        int cnt = min(32, end - e0);
#pragma unroll 4
        for (int j = 0; j < cnt; j++) {
            int   ss = __shfl_sync(0xffffffffu, s,  j);
            float ww = __shfl_sync(0xffffffffu, wt, j);
            float2 r = *(const float2*)(relbase + (size_t)ss * 64);
            acc.x = fmaf(ww, r.x, acc.x);
            acc.y = fmaf(ww, r.y, acc.y);
        }
    }

    float2 sf = *(const float2*)(g_self2 + (size_t)w * 64 + lane * 2);
    float2 kv = *(const float2*)(g_vk2 + lane * 2);
    float2 qv = *(const float2*)(g_vq2 + lane * 2);

    float dsk = sf.x * kv.x + sf.y * kv.y;
    float dnk = acc.x * kv.x + acc.y * kv.y;
    float dsq = sf.x * qv.x + sf.y * qv.y;
#pragma unroll
    for (int off = 16; off; off >>= 1) {
        dsk += __shfl_xor_sync(0xffffffffu, dsk, off);
        dnk += __shfl_xor_sync(0xffffffffu, dnk, off);
        dsq += __shfl_xor_sync(0xffffffffu, dsq, off);
    }
    float es = eluf(dsk + dsq);
    float en = eluf(dnk + dsq);
    float m = fmaxf(es, en);
    float xe = __expf(es - m), ne = __expf(en - m);
    float inv = 1.f / (xe + ne);
    float a0 = xe * inv, a1 = ne * inv;

    float2 b = *(const float2*)(bias + lane * 2);
    float ox = fmaf(a0, sf.x, fmaf(a1, acc.x, b.x));
    float oy = fmaf(a0, sf.y, fmaf(a1, acc.y, b.y));

    int gg = gid[w];
    atomicAdd(&g_gsum[gg * 64 + lane * 2],     ox);
    atomicAdd(&g_gsum[gg * 64 + lane * 2 + 1], oy);

    if (lane == 0) { att_out[2 * w] = a0; att_out[2 * w + 1] = a1; }
}

// ---------------- graph-mean + MLP head (one warp per graph) ----------------
__global__ void mlp_k(const float* __restrict__ w1, const float* __restrict__ b1,
                      const float* __restrict__ w2, const float* __restrict__ b2,
                      float* __restrict__ out) {
    int g = blockIdx.x * (blockDim.x >> 5) + (threadIdx.x >> 5);
    int lane = threadIdx.x & 31;
    if (g >= GG) return;
    float inv = 1.f / fmaxf((float)g_gcnt[g], 1.f);
    // each lane holds hg[lane] and hg[lane+32]
    float h0 = g_gsum[g * 64 + lane] * inv;
    float h1 = g_gsum[g * 64 + 32 + lane] * inv;
    // lane h computes hidden unit h (32 hidden units, one per lane)
    float s = b1[lane];
#pragma unroll
    for (int d = 0; d < 32; d++) {
        float hd0 = __shfl_sync(0xffffffffu, h0, d);
        float hd1 = __shfl_sync(0xffffffffu, h1, d);
        s = fmaf(hd0, w1[d * 32 + lane], s);
        s = fmaf(hd1, w1[(d + 32) * 32 + lane], s);
    }
    s = fmaxf(s, 0.f);
    float partial = s * w2[lane];
#pragma unroll
    for (int off = 16; off; off >>= 1)
        partial += __shfl_xor_sync(0xffffffffu, partial, off);
    if (lane == 0) out[g] = partial + b2[0];
}

// ---------------------------------------------------------------------------
extern "C" void kernel_launch(void* const* d_in, const int* in_sizes, int n_in,
                              void* d_out, int out_size) {
    const float* x       = (const float*)d_in[0];
    const int*   esrc    = (const int*)  d_in[1];
    const int*   edst    = (const int*)  d_in[2];
    const float* ew      = (const float*)d_in[3];
    const int*   gid     = (const int*)  d_in[4];
    const float* w_self1 = (const float*)d_in[5];
    const float* w_rel1  = (const float*)d_in[6];
    const float* bias1   = (const float*)d_in[7];
    const float* w_q1    = (const float*)d_in[8];
    const float* w_k1    = (const float*)d_in[9];
    const float* w_att1  = (const float*)d_in[10];
    const float* w_self2 = (const float*)d_in[11];
    const float* w_rel2  = (const float*)d_in[12];
    const float* bias2   = (const float*)d_in[13];
    const float* w_q2    = (const float*)d_in[14];
    const float* w_k2    = (const float*)d_in[15];
    const float* w_att2  = (const float*)d_in[16];
    const float* mlp_w1  = (const float*)d_in[17];
    const float* mlp_b1  = (const float*)d_in[18];
    const float* mlp_w2  = (const float*)d_in[19];
    const float* mlp_b2  = (const float*)d_in[20];
    float* out = (float*)d_out;

    const int scan_blocks = (NN + 2047) / 2048;   // 49

    // setup: zero counters, attention vectors, CSR build
    zero_k<<<(NN + 255) / 256, 256>>>();
    prep_k<<<1, 128>>>(w_q1, w_k1, w_att1, w_q2, w_k2, w_att2);
    hist_k<<<(EE + 255) / 256, 256>>>(edst, gid);
    scanA_k<<<scan_blocks, 256>>>();
    scanB_k<<<1, 32>>>(scan_blocks);
    scanC_k<<<(NN + 255) / 256, 256>>>();
    fill_k<<<(EE + 255) / 256, 256>>>(esrc, edst, ew);

    // layer 1: fused [self|rel] GEMM, then gather+attention+elu
    gemm_k<<<dim3((NN + 63) / 64, 4), 256>>>(x, 0, w_self1, w_rel1, 128);
    spmm_att1_k<<<(NN * 32 + 255) / 256, 256>>>(bias1, out + 64);

    // layer 2
    gemm_k<<<dim3((NN + 63) / 64, 2), 256>>>(nullptr, 1, w_self2, w_rel2, 64);
    spmm_att2_k<<<(NN * 32 + 255) / 256, 256>>>(bias2, gid, out + 64 + 2 * NN);

    // graph mean + MLP head
    mlp_k<<<2, 1024>>>(mlp_w1, mlp_b1, mlp_w2, mlp_b2, out);
}

// round 7
// speedup vs baseline: 1.0087x; 1.0087x over previous
#include <cuda_runtime.h>
#include <cuda_bf16.h>
#include <math.h>

// ---------------------------------------------------------------------------
// ATT_HGCN: 2-layer attention GCN, fully fused pipeline.
//   N=100000 nodes, E=1600000 edges, D_IN=D_HID=128, D_OUT=64, ATT=64, G=64
// Output layout (float32, 400064 elems):
//   [0:64)                graph_embd (G,1)
//   [64 : 64+2N)          att1 (N,2) row-major
//   [64+2N : 64+4N)       att2 (N,2) row-major
// Pending experiment: GEMM inner loop via packed fma.rn.f32x2 (FFMA2),
// xs transposed [k][m], f32x2 accumulators paired along m.
// ---------------------------------------------------------------------------

static constexpr int NN = 100000;
static constexpr int EE = 1600000;
static constexpr int GG = 64;

// ---------------- scratch (static __device__ — no allocations) -------------
__device__ float g_self1[(size_t)NN * 128];
__device__ float g_rel1 [(size_t)NN * 128];
__device__ float g_h1   [(size_t)NN * 128];
__device__ float g_self2[(size_t)NN * 64];
__device__ float g_rel2 [(size_t)NN * 64];

__device__ int   g_deg[NN];
__device__ int   g_rowptr[NN + 1];
__device__ int   g_cursor[NN];
__device__ int   g_bsum[64];
__device__ int   g_csr_src[EE];
__device__ float g_csr_w[EE];

__device__ float g_vk1[128], g_vq1[128], g_vk2[64], g_vq2[64];
__device__ float g_gsum[GG * 64];
__device__ int   g_gcnt[GG];

__device__ __forceinline__ float eluf(float v) {
    return v > 0.f ? v : (__expf(v) - 1.f);
}

// ---- packed f32x2 helpers (Blackwell sm_103a) ------------------------------
__device__ __forceinline__ unsigned long long pack_dup(float x) {
    unsigned long long r; unsigned int u = __float_as_uint(x);
    asm("mov.b64 %0, {%1, %1};" : "=l"(r) : "r"(u));
    return r;
}
__device__ __forceinline__ void fma2(unsigned long long& d,
                                     unsigned long long a, unsigned long long b) {
    asm("fma.rn.f32x2 %0, %1, %2, %0;" : "+l"(d) : "l"(a), "l"(b));
}
__device__ __forceinline__ void unpack2(unsigned long long v, float& lo, float& hi) {
    asm("mov.b64 {%0, %1}, %2;" : "=f"(lo), "=f"(hi) : "l"(v));
}

// ---------------- small setup kernels ---------------------------------------
__global__ void zero_k() {
    int i = blockIdx.x * blockDim.x + threadIdx.x;
    if (i < NN) g_deg[i] = 0;
    if (i < GG * 64) g_gsum[i] = 0.f;
    if (i < GG) g_gcnt[i] = 0;
}

// vk = w_k @ a[:ATT], vq = w_q @ a[ATT:]
__global__ void prep_k(const float* __restrict__ wq1, const float* __restrict__ wk1,
                       const float* __restrict__ watt1,
                       const float* __restrict__ wq2, const float* __restrict__ wk2,
                       const float* __restrict__ watt2) {
    int d = threadIdx.x;
    if (d < 128) {
        float sk = 0.f, sq = 0.f;
        for (int a = 0; a < 64; a++) {
            sk = fmaf(wk1[d * 64 + a], watt1[a], sk);
            sq = fmaf(wq1[d * 64 + a], watt1[64 + a], sq);
        }
        g_vk1[d] = sk; g_vq1[d] = sq;
    }
    if (d < 64) {
        float sk = 0.f, sq = 0.f;
        for (int a = 0; a < 64; a++) {
            sk = fmaf(wk2[d * 64 + a], watt2[a], sk);
            sq = fmaf(wq2[d * 64 + a], watt2[64 + a], sq);
        }
        g_vk2[d] = sk; g_vq2[d] = sq;
    }
}

__global__ void hist_k(const int* __restrict__ edst, const int* __restrict__ gid) {
    int i = blockIdx.x * blockDim.x + threadIdx.x;
    if (i < EE) atomicAdd(&g_deg[edst[i]], 1);
    if (i < NN) atomicAdd(&g_gcnt[gid[i]], 1);
}

// -------- exclusive scan of g_deg -> g_rowptr (3 phases, 2048 elems/block) ---
__global__ void scanA_k() {
    __shared__ int sh[256];
    int tid = threadIdx.x;
    int base = blockIdx.x * 2048 + tid * 8;
    int v[8]; int run = 0;
#pragma unroll
    for (int j = 0; j < 8; j++) {
        int idx = base + j;
        int d = (idx < NN) ? g_deg[idx] : 0;
        v[j] = run; run += d;
    }
    sh[tid] = run;
    __syncthreads();
    for (int off = 1; off < 256; off <<= 1) {
        int t = (tid >= off) ? sh[tid - off] : 0;
        __syncthreads();
        sh[tid] += t;
        __syncthreads();
    }
    int excl = sh[tid] - run;
#pragma unroll
    for (int j = 0; j < 8; j++) {
        int idx = base + j;
        if (idx < NN) g_rowptr[idx] = excl + v[j];
    }
    if (tid == 255) g_bsum[blockIdx.x] = sh[255];
}

__global__ void scanB_k(int nb) {
    if (threadIdx.x == 0 && blockIdx.x == 0) {
        int run = 0;
        for (int i = 0; i < nb; i++) { int t = g_bsum[i]; g_bsum[i] = run; run += t; }
    }
}

__global__ void scanC_k() {
    int i = blockIdx.x * blockDim.x + threadIdx.x;
    if (i < NN) {
        int r = g_rowptr[i] + g_bsum[i >> 11];
        g_rowptr[i] = r;
        g_cursor[i] = r;
    }
    if (i == 0) g_rowptr[NN] = EE;
}

__global__ void fill_k(const int* __restrict__ esrc, const int* __restrict__ edst,
                       const float* __restrict__ ew) {
    int e = blockIdx.x * blockDim.x + threadIdx.x;
    if (e >= EE) return;
    int d = edst[e];
    int pos = atomicAdd(&g_cursor[d], 1);
    g_csr_src[pos] = esrc[e];
    g_csr_w[pos]   = ew[e];
}

// ---------------- fused GEMM: C = X @ W via packed f32x2 FMA ----------------
// X: [NN][128]  (layer==0: harness x; layer==1: g_h1)
// Wa/Wb: [128][half] each. Column tile picks Wa or Wb. 64x64 tile, 4x4/thread.
// xs is stored TRANSPOSED [k][m] so each m-pair loads as one 64-bit LDS;
// accumulators are f32x2 pairs along m. Per k per thread:
//   8 FFMA2 + 2 LDS.64 (x pairs) + 1 LDS.128 (w) + 4 packs = 15 issues,
//   16 fma-pipe cycles -> FMA-bound at 2x scalar-FFMA throughput.
__global__ void __launch_bounds__(256, 4)
gemm_k(const float* __restrict__ Xext, int layer,
       const float* __restrict__ Wa, const float* __restrict__ Wb, int half) {
    const float* __restrict__ X = (layer == 0) ? Xext : g_h1;
    float* Ca = (layer == 0) ? g_self1 : g_self2;
    float* Cb = (layer == 0) ? g_rel1  : g_rel2;

    int colbase = blockIdx.y * 64;
    const float* __restrict__ W;
    float* C; int cb;
    if (colbase < half) { W = Wa; C = Ca; cb = colbase; }
    else                { W = Wb; C = Cb; cb = colbase - half; }

    __shared__ float xs[64][66];   // TRANSPOSED: [k][m], stride 66 keeps 8B align
    __shared__ float ws[64][64];   // [k][n]

    int tid = threadIdx.x;
    int tx = tid & 15, ty = tid >> 4;
    int m0 = blockIdx.x * 64;
    int ty4 = ty * 4, tx4 = tx * 4;

    unsigned long long acc2[2][4];   // [m-pair][n]: (row ty4+2p, row ty4+2p+1)
#pragma unroll
    for (int p = 0; p < 2; p++)
#pragma unroll
        for (int j = 0; j < 4; j++) acc2[p][j] = 0ull;

    for (int kc = 0; kc < 128; kc += 64) {
        // stage X tile transposed: read [m][k] float4, write xs[k][m]
#pragma unroll
        for (int li = tid; li < 1024; li += 256) {
            int r = li >> 4, c4 = (li & 15) << 2;   // r = m index, c4 = k base
            int gm = m0 + r;
            float4 v = make_float4(0.f, 0.f, 0.f, 0.f);
            if (gm < NN) v = *(const float4*)(X + (size_t)gm * 128 + kc + c4);
            xs[c4 + 0][r] = v.x; xs[c4 + 1][r] = v.y;
            xs[c4 + 2][r] = v.z; xs[c4 + 3][r] = v.w;
        }
        // stage W tile (64 k-rows x 64 cols)
#pragma unroll
        for (int li = tid; li < 1024; li += 256) {
            int r = li >> 4, c4 = (li & 15) << 2;
            *(float4*)(&ws[r][c4]) = *(const float4*)(W + (size_t)(kc + r) * half + cb + c4);
        }
        __syncthreads();
#pragma unroll 16
        for (int k = 0; k < 64; k++) {
            unsigned long long xp0 = *(const unsigned long long*)(&xs[k][ty4]);
            unsigned long long xp1 = *(const unsigned long long*)(&xs[k][ty4 + 2]);
            float4 wv = *(const float4*)(&ws[k][tx4]);
            unsigned long long w0 = pack_dup(wv.x);
            unsigned long long w1 = pack_dup(wv.y);
            unsigned long long w2 = pack_dup(wv.z);
            unsigned long long w3 = pack_dup(wv.w);
            fma2(acc2[0][0], xp0, w0); fma2(acc2[0][1], xp0, w1);
            fma2(acc2[0][2], xp0, w2); fma2(acc2[0][3], xp0, w3);
            fma2(acc2[1][0], xp1, w0); fma2(acc2[1][1], xp1, w1);
            fma2(acc2[1][2], xp1, w2); fma2(acc2[1][3], xp1, w3);
        }
        __syncthreads();
    }
    // epilogue: unpack pairs -> rows
#pragma unroll
    for (int p = 0; p < 2; p++) {
        float lo0, hi0, lo1, hi1, lo2, hi2, lo3, hi3;
        unpack2(acc2[p][0], lo0, hi0);
        unpack2(acc2[p][1], lo1, hi1);
        unpack2(acc2[p][2], lo2, hi2);
        unpack2(acc2[p][3], lo3, hi3);
        int gmA = m0 + ty4 + 2 * p;
        int gmB = gmA + 1;
        if (gmA < NN)
            *(float4*)(C + (size_t)gmA * half + cb + tx4) = make_float4(lo0, lo1, lo2, lo3);
        if (gmB < NN)
            *(float4*)(C + (size_t)gmB * half + cb + tx4) = make_float4(hi0, hi1, hi2, hi3);
    }
}

// ------------- fused SpMM gather + attention + elu, layer 1 (D=128) ---------
// One warp per dst node; nb row lives in registers (4 floats/lane).
__global__ void spmm_att1_k(const float* __restrict__ bias, float* __restrict__ att_out) {
    int w = (blockIdx.x * blockDim.x + threadIdx.x) >> 5;
    int lane = threadIdx.x & 31;
    if (w >= NN) return;

    int beg = g_rowptr[w], end = g_rowptr[w + 1];
    float4 acc = make_float4(0.f, 0.f, 0.f, 0.f);
    const float* __restrict__ relbase = g_rel1 + lane * 4;

    for (int e0 = beg; e0 < end; e0 += 32) {
        int e = e0 + lane;
        int s = 0; float wt = 0.f;
        if (e < end) { s = g_csr_src[e]; wt = g_csr_w[e]; }
        int cnt = min(32, end - e0);
#pragma unroll 4
        for (int j = 0; j < cnt; j++) {
            int   ss = __shfl_sync(0xffffffffu, s,  j);
            float ww = __shfl_sync(0xffffffffu, wt, j);
            float4 r = *(const float4*)(relbase + (size_t)ss * 128);
            acc.x = fmaf(ww, r.x, acc.x);
            acc.y = fmaf(ww, r.y, acc.y);
            acc.z = fmaf(ww, r.z, acc.z);
            acc.w = fmaf(ww, r.w, acc.w);
        }
    }

    float4 sf = *(const float4*)(g_self1 + (size_t)w * 128 + lane * 4);
    float4 kv = *(const float4*)(g_vk1 + lane * 4);
    float4 qv = *(const float4*)(g_vq1 + lane * 4);

    float dsk = sf.x * kv.x + sf.y * kv.y + sf.z * kv.z + sf.w * kv.w;
    float dnk = acc.x * kv.x + acc.y * kv.y + acc.z * kv.z + acc.w * kv.w;
    float dsq = sf.x * qv.x + sf.y * qv.y + sf.z * qv.z + sf.w * qv.w;
#pragma unroll
    for (int off = 16; off; off >>= 1) {
        dsk += __shfl_xor_sync(0xffffffffu, dsk, off);
        dnk += __shfl_xor_sync(0xffffffffu, dnk, off);
        dsq += __shfl_xor_sync(0xffffffffu, dsq, off);
    }
    float es = eluf(dsk + dsq);
    float en = eluf(dnk + dsq);
    float m = fmaxf(es, en);
    float xe = __expf(es - m), ne = __expf(en - m);
    float inv = 1.f / (xe + ne);
    float a0 = xe * inv, a1 = ne * inv;

    float4 b = *(const float4*)(bias + lane * 4);
    float4 o;
    o.x = eluf(fmaf(a0, sf.x, fmaf(a1, acc.x, b.x)));
    o.y = eluf(fmaf(a0, sf.y, fmaf(a1, acc.y, b.y)));
    o.z = eluf(fmaf(a0, sf.z, fmaf(a1, acc.z, b.z)));
    o.w = eluf(fmaf(a0, sf.w, fmaf(a1, acc.w, b.w)));
    *(float4*)(g_h1 + (size_t)w * 128 + lane * 4) = o;

    if (lane == 0) { att_out[2 * w] = a0; att_out[2 * w + 1] = a1; }
}

// ------- fused SpMM + attention, layer 2 (D=64) + graph-sum pooling ---------
__global__ void spmm_att2_k(const float* __restrict__ bias, const int* __restrict__ gid,
                            float* __restrict__ att_out) {
    int w = (blockIdx.x * blockDim.x + threadIdx.x) >> 5;
    int lane = threadIdx.x & 31;
    if (w >= NN) return;

    int beg = g_rowptr[w], end = g_rowptr[w + 1];
    float2 acc = make_float2(0.f, 0.f);
    const float* __restrict__ relbase = g_rel2 + lane * 2;

    for (int e0 = beg; e0 < end; e0 += 32) {
        int e = e0 + lane;
        int s = 0; float wt = 0.f;
        if (e < end) { s = g_csr_src[e]; wt = g_csr_w[e]; }
        int cnt = min(32, end - e0);
#pragma unroll 4
        for (int j = 0; j < cnt; j++) {
            int   ss = __shfl_sync(0xffffffffu, s,  j);
            float ww = __shfl_sync(0xffffffffu, wt, j);
            float2 r = *(const float2*)(relbase + (size_t)ss * 64);
            acc.x = fmaf(ww, r.x, acc.x);
            acc.y = fmaf(ww, r.y, acc.y);
        }
    }

    float2 sf = *(const float2*)(g_self2 + (size_t)w * 64 + lane * 2);
    float2 kv = *(const float2*)(g_vk2 + lane * 2);
    float2 qv = *(const float2*)(g_vq2 + lane * 2);

    float dsk = sf.x * kv.x + sf.y * kv.y;
    float dnk = acc.x * kv.x + acc.y * kv.y;
    float dsq = sf.x * qv.x + sf.y * qv.y;
#pragma unroll
    for (int off = 16; off; off >>= 1) {
        dsk += __shfl_xor_sync(0xffffffffu, dsk, off);
        dnk += __shfl_xor_sync(0xffffffffu, dnk, off);
        dsq += __shfl_xor_sync(0xffffffffu, dsq, off);
    }
    float es = eluf(dsk + dsq);
    float en = eluf(dnk + dsq);
    float m = fmaxf(es, en);
    float xe = __expf(es - m), ne = __expf(en - m);
    float inv = 1.f / (xe + ne);
    float a0 = xe * inv, a1 = ne * inv;

    float2 b = *(const float2*)(bias + lane * 2);
    float ox = fmaf(a0, sf.x, fmaf(a1, acc.x, b.x));
    float oy = fmaf(a0, sf.y, fmaf(a1, acc.y, b.y));

    int gg = gid[w];
    atomicAdd(&g_gsum[gg * 64 + lane * 2],     ox);
    atomicAdd(&g_gsum[gg * 64 + lane * 2 + 1], oy);

    if (lane == 0) { att_out[2 * w] = a0; att_out[2 * w + 1] = a1; }
}

// ---------------- graph-mean + MLP head (one warp per graph) ----------------
__global__ void mlp_k(const float* __restrict__ w1, const float* __restrict__ b1,
                      const float* __restrict__ w2, const float* __restrict__ b2,
                      float* __restrict__ out) {
    int g = blockIdx.x * (blockDim.x >> 5) + (threadIdx.x >> 5);
    int lane = threadIdx.x & 31;
    if (g >= GG) return;
    float inv = 1.f / fmaxf((float)g_gcnt[g], 1.f);
    float h0 = g_gsum[g * 64 + lane] * inv;
    float h1 = g_gsum[g * 64 + 32 + lane] * inv;
    float s = b1[lane];
#pragma unroll
    for (int d = 0; d < 32; d++) {
        float hd0 = __shfl_sync(0xffffffffu, h0, d);
        float hd1 = __shfl_sync(0xffffffffu, h1, d);
        s = fmaf(hd0, w1[d * 32 + lane], s);
        s = fmaf(hd1, w1[(d + 32) * 32 + lane], s);
    }
    s = fmaxf(s, 0.f);
    float partial = s * w2[lane];
#pragma unroll
    for (int off = 16; off; off >>= 1)
        partial += __shfl_xor_sync(0xffffffffu, partial, off);
    if (lane == 0) out[g] = partial + b2[0];
}

// ---------------------------------------------------------------------------
extern "C" void kernel_launch(void* const* d_in, const int* in_sizes, int n_in,
                              void* d_out, int out_size) {
    const float* x       = (const float*)d_in[0];
    const int*   esrc    = (const int*)  d_in[1];
    const int*   edst    = (const int*)  d_in[2];
    const float* ew      = (const float*)d_in[3];
    const int*   gid     = (const int*)  d_in[4];
    const float* w_self1 = (const float*)d_in[5];
    const float* w_rel1  = (const float*)d_in[6];
    const float* bias1   = (const float*)d_in[7];
    const float* w_q1    = (const float*)d_in[8];
    const float* w_k1    = (const float*)d_in[9];
    const float* w_att1  = (const float*)d_in[10];
    const float* w_self2 = (const float*)d_in[11];
    const float* w_rel2  = (const float*)d_in[12];
    const float* bias2   = (const float*)d_in[13];
    const float* w_q2    = (const float*)d_in[14];
    const float* w_k2    = (const float*)d_in[15];
    const float* w_att2  = (const float*)d_in[16];
    const float* mlp_w1  = (const float*)d_in[17];
    const float* mlp_b1  = (const float*)d_in[18];
    const float* mlp_w2  = (const float*)d_in[19];
    const float* mlp_b2  = (const float*)d_in[20];
    float* out = (float*)d_out;

    const int scan_blocks = (NN + 2047) / 2048;   // 49

    // setup: zero counters, attention vectors, CSR build
    zero_k<<<(NN + 255) / 256, 256>>>();
    prep_k<<<1, 128>>>(w_q1, w_k1, w_att1, w_q2, w_k2, w_att2);
    hist_k<<<(EE + 255) / 256, 256>>>(edst, gid);
    scanA_k<<<scan_blocks, 256>>>();
    scanB_k<<<1, 64>>>(scan_blocks);
    scanC_k<<<(NN + 255) / 256, 256>>>();
    fill_k<<<(EE + 255) / 256, 256>>>(esrc, edst, ew);

    // layer 1: fused [self|rel] GEMM, then gather+attention+elu
    gemm_k<<<dim3((NN + 63) / 64, 4), 256>>>(x, 0, w_self1, w_rel1, 128);
    spmm_att1_k<<<(NN * 32 + 255) / 256, 256>>>(bias1, out + 64);

    // layer 2
    gemm_k<<<dim3((NN + 63) / 64, 2), 256>>>(nullptr, 1, w_self2, w_rel2, 64);
    spmm_att2_k<<<(NN * 32 + 255) / 256, 256>>>(bias2, gid, out + 64 + 2 * NN);

    // graph mean + MLP head
    mlp_k<<<2, 1024>>>(mlp_w1, mlp_b1, mlp_w2, mlp_b2, out);
}

// round 9
// speedup vs baseline: 1.0200x; 1.0112x over previous
#include <cuda_runtime.h>
#include <cuda_bf16.h>
#include <math.h>

// ---------------------------------------------------------------------------
// ATT_HGCN: 2-layer attention GCN, fully fused pipeline.
//   N=100000 nodes, E=1600000 edges, D_IN=D_HID=128, D_OUT=64, ATT=64, G=64
// Output layout (float32, 400064 elems):
//   [0:64) graph_embd | [64:64+2N) att1 | [64+2N:64+4N) att2
// Pending: gemm1 at 4th launch (ncu capture slot) for phase attribution;
//          CSR packed as int2 {src, w_bits}.
// ---------------------------------------------------------------------------

static constexpr int NN = 100000;
static constexpr int EE = 1600000;
static constexpr int GG = 64;

// ---------------- scratch (static __device__ — no allocations) -------------
__device__ float g_self1[(size_t)NN * 128];
__device__ float g_rel1 [(size_t)NN * 128];
__device__ float g_h1   [(size_t)NN * 128];
__device__ float g_self2[(size_t)NN * 64];
__device__ float g_rel2 [(size_t)NN * 64];

__device__ int   g_deg[NN];
__device__ int   g_rowptr[NN + 1];
__device__ int   g_cursor[NN];
__device__ int   g_bsum[64];
__device__ int2  g_csr[EE];          // {src, __float_as_int(w)}

__device__ float g_vk1[128], g_vq1[128], g_vk2[64], g_vq2[64];
__device__ float g_gsum[GG * 64];
__device__ int   g_gcnt[GG];

__device__ __forceinline__ float eluf(float v) {
    return v > 0.f ? v : (__expf(v) - 1.f);
}

// ---- packed f32x2 helpers (Blackwell sm_103a) ------------------------------
__device__ __forceinline__ unsigned long long pack_dup(float x) {
    unsigned long long r; unsigned int u = __float_as_uint(x);
    asm("mov.b64 %0, {%1, %1};" : "=l"(r) : "r"(u));
    return r;
}
__device__ __forceinline__ void fma2(unsigned long long& d,
                                     unsigned long long a, unsigned long long b) {
    asm("fma.rn.f32x2 %0, %1, %2, %0;" : "+l"(d) : "l"(a), "l"(b));
}
__device__ __forceinline__ void unpack2(unsigned long long v, float& lo, float& hi) {
    asm("mov.b64 {%0, %1}, %2;" : "=f"(lo), "=f"(hi) : "l"(v));
}

// ---------------- small setup kernels ---------------------------------------
__global__ void zero_k() {
    int i = blockIdx.x * blockDim.x + threadIdx.x;
    if (i < NN) g_deg[i] = 0;
    if (i < GG * 64) g_gsum[i] = 0.f;
    if (i < GG) g_gcnt[i] = 0;
}

// vk = w_k @ a[:ATT], vq = w_q @ a[ATT:]
__global__ void prep_k(const float* __restrict__ wq1, const float* __restrict__ wk1,
                       const float* __restrict__ watt1,
                       const float* __restrict__ wq2, const float* __restrict__ wk2,
                       const float* __restrict__ watt2) {
    int d = threadIdx.x;
    if (d < 128) {
        float sk = 0.f, sq = 0.f;
        for (int a = 0; a < 64; a++) {
            sk = fmaf(wk1[d * 64 + a], watt1[a], sk);
            sq = fmaf(wq1[d * 64 + a], watt1[64 + a], sq);
        }
        g_vk1[d] = sk; g_vq1[d] = sq;
    }
    if (d < 64) {
        float sk = 0.f, sq = 0.f;
        for (int a = 0; a < 64; a++) {
            sk = fmaf(wk2[d * 64 + a], watt2[a], sk);
            sq = fmaf(wq2[d * 64 + a], watt2[64 + a], sq);
        }
        g_vk2[d] = sk; g_vq2[d] = sq;
    }
}

__global__ void hist_k(const int* __restrict__ edst, const int* __restrict__ gid) {
    int i = blockIdx.x * blockDim.x + threadIdx.x;
    if (i < EE) atomicAdd(&g_deg[edst[i]], 1);
    if (i < NN) atomicAdd(&g_gcnt[gid[i]], 1);
}

// -------- exclusive scan of g_deg -> g_rowptr (3 phases, 2048 elems/block) ---
__global__ void scanA_k() {
    __shared__ int sh[256];
    int tid = threadIdx.x;
    int base = blockIdx.x * 2048 + tid * 8;
    int v[8]; int run = 0;
#pragma unroll
    for (int j = 0; j < 8; j++) {
        int idx = base + j;
        int d = (idx < NN) ? g_deg[idx] : 0;
        v[j] = run; run += d;
    }
    sh[tid] = run;
    __syncthreads();
    for (int off = 1; off < 256; off <<= 1) {
        int t = (tid >= off) ? sh[tid - off] : 0;
        __syncthreads();
        sh[tid] += t;
        __syncthreads();
    }
    int excl = sh[tid] - run;
#pragma unroll
    for (int j = 0; j < 8; j++) {
        int idx = base + j;
        if (idx < NN) g_rowptr[idx] = excl + v[j];
    }
    if (tid == 255) g_bsum[blockIdx.x] = sh[255];
}

__global__ void scanB_k(int nb) {
    if (threadIdx.x == 0 && blockIdx.x == 0) {
        int run = 0;
        for (int i = 0; i < nb; i++) { int t = g_bsum[i]; g_bsum[i] = run; run += t; }
    }
}

__global__ void scanC_k() {
    int i = blockIdx.x * blockDim.x + threadIdx.x;
    if (i < NN) {
        int r = g_rowptr[i] + g_bsum[i >> 11];
        g_rowptr[i] = r;
        g_cursor[i] = r;
    }
    if (i == 0) g_rowptr[NN] = EE;
}

__global__ void fill_k(const int* __restrict__ esrc, const int* __restrict__ edst,
                       const float* __restrict__ ew) {
    int e = blockIdx.x * blockDim.x + threadIdx.x;
    if (e >= EE) return;
    int d = edst[e];
    int pos = atomicAdd(&g_cursor[d], 1);
    g_csr[pos] = make_int2(esrc[e], __float_as_int(ew[e]));
}

// ---------------- fused GEMM: C = X @ W via packed f32x2 FMA ----------------
// X: [NN][128]  (layer==0: harness x; layer==1: g_h1)
// Wa/Wb: [128][half] each. Column tile picks Wa or Wb. 64x64 tile, 4x4/thread.
__global__ void __launch_bounds__(256, 4)
gemm_k(const float* __restrict__ Xext, int layer,
       const float* __restrict__ Wa, const float* __restrict__ Wb, int half) {
    const float* __restrict__ X = (layer == 0) ? Xext : g_h1;
    float* Ca = (layer == 0) ? g_self1 : g_self2;
    float* Cb = (layer == 0) ? g_rel1  : g_rel2;

    int colbase = blockIdx.y * 64;
    const float* __restrict__ W;
    float* C; int cb;
    if (colbase < half) { W = Wa; C = Ca; cb = colbase; }
    else                { W = Wb; C = Cb; cb = colbase - half; }

    __shared__ float xs[64][66];   // TRANSPOSED: [k][m], stride 66 keeps 8B align
    __shared__ float ws[64][64];   // [k][n]

    int tid = threadIdx.x;
    int tx = tid & 15, ty = tid >> 4;
    int m0 = blockIdx.x * 64;
    int ty4 = ty * 4, tx4 = tx * 4;

    unsigned long long acc2[2][4];
#pragma unroll
    for (int p = 0; p < 2; p++)
#pragma unroll
        for (int j = 0; j < 4; j++) acc2[p][j] = 0ull;

    for (int kc = 0; kc < 128; kc += 64) {
#pragma unroll
        for (int li = tid; li < 1024; li += 256) {
            int r = li >> 4, c4 = (li & 15) << 2;
            int gm = m0 + r;
            float4 v = make_float4(0.f, 0.f, 0.f, 0.f);
            if (gm < NN) v = *(const float4*)(X + (size_t)gm * 128 + kc + c4);
            xs[c4 + 0][r] = v.x; xs[c4 + 1][r] = v.y;
            xs[c4 + 2][r] = v.z; xs[c4 + 3][r] = v.w;
        }
#pragma unroll
        for (int li = tid; li < 1024; li += 256) {
            int r = li >> 4, c4 = (li & 15) << 2;
            *(float4*)(&ws[r][c4]) = *(const float4*)(W + (size_t)(kc + r) * half + cb + c4);
        }
        __syncthreads();
#pragma unroll 16
        for (int k = 0; k < 64; k++) {
            unsigned long long xp0 = *(const unsigned long long*)(&xs[k][ty4]);
            unsigned long long xp1 = *(const unsigned long long*)(&xs[k][ty4 + 2]);
            float4 wv = *(const float4*)(&ws[k][tx4]);
            unsigned long long w0 = pack_dup(wv.x);
            unsigned long long w1 = pack_dup(wv.y);
            unsigned long long w2 = pack_dup(wv.z);
            unsigned long long w3 = pack_dup(wv.w);
            fma2(acc2[0][0], xp0, w0); fma2(acc2[0][1], xp0, w1);
            fma2(acc2[0][2], xp0, w2); fma2(acc2[0][3], xp0, w3);
            fma2(acc2[1][0], xp1, w0); fma2(acc2[1][1], xp1, w1);
            fma2(acc2[1][2], xp1, w2); fma2(acc2[1][3], xp1, w3);
        }
        __syncthreads();
    }
#pragma unroll
    for (int p = 0; p < 2; p++) {
        float lo0, hi0, lo1, hi1, lo2, hi2, lo3, hi3;
        unpack2(acc2[p][0], lo0, hi0);
        unpack2(acc2[p][1], lo1, hi1);
        unpack2(acc2[p][2], lo2, hi2);
        unpack2(acc2[p][3], lo3, hi3);
        int gmA = m0 + ty4 + 2 * p;
        int gmB = gmA + 1;
        if (gmA < NN)
            *(float4*)(C + (size_t)gmA * half + cb + tx4) = make_float4(lo0, lo1, lo2, lo3);
        if (gmB < NN)
            *(float4*)(C + (size_t)gmB * half + cb + tx4) = make_float4(hi0, hi1, hi2, hi3);
    }
}

// ------------- fused SpMM gather + attention + elu, layer 1 (D=128) ---------
__global__ void spmm_att1_k(const float* __restrict__ bias, float* __restrict__ att_out) {
    int w = (blockIdx.x * blockDim.x + threadIdx.x) >> 5;
    int lane = threadIdx.x & 31;
    if (w >= NN) return;

    int beg = g_rowptr[w], end = g_rowptr[w + 1];
    float4 acc = make_float4(0.f, 0.f, 0.f, 0.f);
    const float* __restrict__ relbase = g_rel1 + lane * 4;

    for (int e0 = beg; e0 < end; e0 += 32) {
        int e = e0 + lane;
        int2 ed = make_int2(0, 0);
        if (e < end) ed = g_csr[e];
        int cnt = min(32, end - e0);
#pragma unroll 4
        for (int j = 0; j < cnt; j++) {
            int   ss = __shfl_sync(0xffffffffu, ed.x, j);
            float ww = __int_as_float(__shfl_sync(0xffffffffu, ed.y, j));
            float4 r = *(const float4*)(relbase + (size_t)ss * 128);
            acc.x = fmaf(ww, r.x, acc.x);
            acc.y = fmaf(ww, r.y, acc.y);
            acc.z = fmaf(ww, r.z, acc.z);
            acc.w = fmaf(ww, r.w, acc.w);
        }
    }

    float4 sf = *(const float4*)(g_self1 + (size_t)w * 128 + lane * 4);
    float4 kv = *(const float4*)(g_vk1 + lane * 4);
    float4 qv = *(const float4*)(g_vq1 + lane * 4);

    float dsk = sf.x * kv.x + sf.y * kv.y + sf.z * kv.z + sf.w * kv.w;
    float dnk = acc.x * kv.x + acc.y * kv.y + acc.z * kv.z + acc.w * kv.w;
    float dsq = sf.x * qv.x + sf.y * qv.y + sf.z * qv.z + sf.w * qv.w;
#pragma unroll
    for (int off = 16; off; off >>= 1) {
        dsk += __shfl_xor_sync(0xffffffffu, dsk, off);
        dnk += __shfl_xor_sync(0xffffffffu, dnk, off);
        dsq += __shfl_xor_sync(0xffffffffu, dsq, off);
    }
    float es = eluf(dsk + dsq);
    float en = eluf(dnk + dsq);
    float m = fmaxf(es, en);
    float xe = __expf(es - m), ne = __expf(en - m);
    float inv = 1.f / (xe + ne);
    float a0 = xe * inv, a1 = ne * inv;

    float4 b = *(const float4*)(bias + lane * 4);
    float4 o;
    o.x = eluf(fmaf(a0, sf.x, fmaf(a1, acc.x, b.x)));
    o.y = eluf(fmaf(a0, sf.y, fmaf(a1, acc.y, b.y)));
    o.z = eluf(fmaf(a0, sf.z, fmaf(a1, acc.z, b.z)));
    o.w = eluf(fmaf(a0, sf.w, fmaf(a1, acc.w, b.w)));
    *(float4*)(g_h1 + (size_t)w * 128 + lane * 4) = o;

    if (lane == 0) { att_out[2 * w] = a0; att_out[2 * w + 1] = a1; }
}

// ------- fused SpMM + attention, layer 2 (D=64) + graph-sum pooling ---------
__global__ void spmm_att2_k(const float* __restrict__ bias, const int* __restrict__ gid,
                            float* __restrict__ att_out) {
    int w = (blockIdx.x * blockDim.x + threadIdx.x) >> 5;
    int lane = threadIdx.x & 31;
    if (w >= NN) return;

    int beg = g_rowptr[w], end = g_rowptr[w + 1];
    float2 acc = make_float2(0.f, 0.f);
    const float* __restrict__ relbase = g_rel2 + lane * 2;

    for (int e0 = beg; e0 < end; e0 += 32) {
        int e = e0 + lane;
        int2 ed = make_int2(0, 0);
        if (e < end) ed = g_csr[e];
        int cnt = min(32, end - e0);
#pragma unroll 4
        for (int j = 0; j < cnt; j++) {
            int   ss = __shfl_sync(0xffffffffu, ed.x, j);
            float ww = __int_as_float(__shfl_sync(0xffffffffu, ed.y, j));
            float2 r = *(const float2*)(relbase + (size_t)ss * 64);
            acc.x = fmaf(ww, r.x, acc.x);
            acc.y = fmaf(ww, r.y, acc.y);
        }
    }

    float2 sf = *(const float2*)(g_self2 + (size_t)w * 64 + lane * 2);
    float2 kv = *(const float2*)(g_vk2 + lane * 2);
    float2 qv = *(const float2*)(g_vq2 + lane * 2);

    float dsk = sf.x * kv.x + sf.y * kv.y;
    float dnk = acc.x * kv.x + acc.y * kv.y;
    float dsq = sf.x * qv.x + sf.y * qv.y;
#pragma unroll
    for (int off = 16; off; off >>= 1) {
        dsk += __shfl_xor_sync(0xffffffffu, dsk, off);
        dnk += __shfl_xor_sync(0xffffffffu, dnk, off);
        dsq += __shfl_xor_sync(0xffffffffu, dsq, off);
    }
    float es = eluf(dsk + dsq);
    float en = eluf(dnk + dsq);
    float m = fmaxf(es, en);
    float xe = __expf(es - m), ne = __expf(en - m);
    float inv = 1.f / (xe + ne);
    float a0 = xe * inv, a1 = ne * inv;

    float2 b = *(const float2*)(bias + lane * 2);
    float ox = fmaf(a0, sf.x, fmaf(a1, acc.x, b.x));
    float oy = fmaf(a0, sf.y, fmaf(a1, acc.y, b.y));

    int gg = gid[w];
    atomicAdd(&g_gsum[gg * 64 + lane * 2],     ox);
    atomicAdd(&g_gsum[gg * 64 + lane * 2 + 1], oy);

    if (lane == 0) { att_out[2 * w] = a0; att_out[2 * w + 1] = a1; }
}

// ---------------- graph-mean + MLP head (one warp per graph) ----------------
__global__ void mlp_k(const float* __restrict__ w1, const float* __restrict__ b1,
                      const float* __restrict__ w2, const float* __restrict__ b2,
                      float* __restrict__ out) {
    int g = blockIdx.x * (blockDim.x >> 5) + (threadIdx.x >> 5);
    int lane = threadIdx.x & 31;
    if (g >= GG) return;
    float inv = 1.f / fmaxf((float)g_gcnt[g], 1.f);
    float h0 = g_gsum[g * 64 + lane] * inv;
    float h1 = g_gsum[g * 64 + 32 + lane] * inv;
    float s = b1[lane];
#pragma unroll
    for (int d = 0; d < 32; d++) {
        float hd0 = __shfl_sync(0xffffffffu, h0, d);
        float hd1 = __shfl_sync(0xffffffffu, h1, d);
        s = fmaf(hd0, w1[d * 32 + lane], s);
        s = fmaf(hd1, w1[(d + 32) * 32 + lane], s);
    }
    s = fmaxf(s, 0.f);
    float partial = s * w2[lane];
#pragma unroll
    for (int off = 16; off; off >>= 1)
        partial += __shfl_xor_sync(0xffffffffu, partial, off);
    if (lane == 0) out[g] = partial + b2[0];
}

// ---------------------------------------------------------------------------
extern "C" void kernel_launch(void* const* d_in, const int* in_sizes, int n_in,
                              void* d_out, int out_size) {
    const float* x       = (const float*)d_in[0];
    const int*   esrc    = (const int*)  d_in[1];
    const int*   edst    = (const int*)  d_in[2];
    const float* ew      = (const float*)d_in[3];
    const int*   gid     = (const int*)  d_in[4];
    const float* w_self1 = (const float*)d_in[5];
    const float* w_rel1  = (const float*)d_in[6];
    const float* bias1   = (const float*)d_in[7];
    const float* w_q1    = (const float*)d_in[8];
    const float* w_k1    = (const float*)d_in[9];
    const float* w_att1  = (const float*)d_in[10];
    const float* w_self2 = (const float*)d_in[11];
    const float* w_rel2  = (const float*)d_in[12];
    const float* bias2   = (const float*)d_in[13];
    const float* w_q2    = (const float*)d_in[14];
    const float* w_k2    = (const float*)d_in[15];
    const float* w_att2  = (const float*)d_in[16];
    const float* mlp_w1  = (const float*)d_in[17];
    const float* mlp_b1  = (const float*)d_in[18];
    const float* mlp_w2  = (const float*)d_in[19];
    const float* mlp_b2  = (const float*)d_in[20];
    float* out = (float*)d_out;

    const int scan_blocks = (NN + 2047) / 2048;   // 49

    // setup + DIAGNOSTIC ORDER: gemm1 is the 4th launch -> lands in the
    // fixed ncu capture slot (both prior profiles captured launch #4, scanA).
    zero_k<<<(NN + 255) / 256, 256>>>();
    prep_k<<<1, 128>>>(w_q1, w_k1, w_att1, w_q2, w_k2, w_att2);
    hist_k<<<(EE + 255) / 256, 256>>>(edst, gid);
    gemm_k<<<dim3((NN + 63) / 64, 4), 256>>>(x, 0, w_self1, w_rel1, 128);  // 4th
    scanA_k<<<scan_blocks, 256>>>();
    scanB_k<<<1, 64>>>(scan_blocks);
    scanC_k<<<(NN + 255) / 256, 256>>>();
    fill_k<<<(EE + 255) / 256, 256>>>(esrc, edst, ew);

    // layer 1 gather+attention+elu (needs gemm1 + CSR)
    spmm_att1_k<<<(NN * 32 + 255) / 256, 256>>>(bias1, out + 64);

    // layer 2
    gemm_k<<<dim3((NN + 63) / 64, 2), 256>>>(nullptr, 1, w_self2, w_rel2, 64);
    spmm_att2_k<<<(NN * 32 + 255) / 256, 256>>>(bias2, gid, out + 64 + 2 * NN);

    // graph mean + MLP head
    mlp_k<<<2, 1024>>>(mlp_w1, mlp_b1, mlp_w2, mlp_b2, out);
}